// round 15
// baseline (speedup 1.0000x reference)
#include <cuda_runtime.h>
#include <cuda_fp16.h>
#include <cstdint>

// ---------------- problem constants ----------------
#define DB   4
#define DS   2048
#define DD   4096
#define DT   256
#define DW   32
#define DH_  512
#define NH   8
#define NTOK (DB*DS)            // 8192
#define NQ   (DB*DT)            // 1024
#define SCL  0.044194173824159216f  // 1/sqrt(512)

typedef __half hf;

// ---------------- device scratch ----------------
__device__ __align__(16) hf b_qkv_h [(long)NTOK*3*DD];
__device__ __align__(16) hf b_y_h   [(long)NTOK*DD];
__device__ __align__(16) hf b_scr_h [(long)DB*NH*DT*DS];
__device__ __align__(16) hf b_yg_h  [(long)NQ*DD];
__device__ __align__(16) hf b_vlm_h  [(long)NTOK*DD];
__device__ __align__(16) hf b_liw_h  [(long)3*DD*DD];
__device__ __align__(16) hf b_low_h  [(long)DD*DD];
__device__ __align__(16) hf b_lpw_h  [(long)DD*DD];
__device__ __align__(16) hf b_giw_h  [(long)3*DD*DD];
__device__ __align__(16) hf b_gow_h  [(long)DD*DD];
__device__ __align__(16) hf b_opw_h  [(long)DD*DD];
__device__ __align__(16) hf b_attnl_h[(long)NTOK*DD];
__device__ __align__(16) hf b_ln_h   [(long)NTOK*DD];
__device__ __align__(16) hf b_lf_h   [(long)NTOK*DD];
__device__ __align__(16) hf b_qtok_h [(long)DT*DD],        b_qtok_l [(long)DT*DD];
__device__ __align__(16) hf b_qg_h   [(long)DT*DD];
__device__ __align__(16) hf b_kvk_h  [(long)NTOK*DD];
__device__ __align__(16) hf b_vt_h   [(long)DB*DD*DS];
__device__ __align__(16) hf b_sc_h   [(long)DB*NH*DT*DS];
__device__ __align__(16) hf b_ag_h   [(long)NQ*DD];
__device__ __align__(16) hf b_lng_h  [(long)NQ*DD];

// ======================= helpers =======================
__device__ __forceinline__ uint32_t smem_u32(const void* p) {
    uint32_t a;
    asm("{ .reg .u64 t; cvta.to.shared.u64 t, %1; cvt.u32.u64 %0, t; }" : "=r"(a) : "l"(p));
    return a;
}
__device__ __forceinline__ void cp16(uint32_t dst, const void* src) {
    asm volatile("cp.async.cg.shared.global [%0], [%1], 16;" :: "r"(dst), "l"(src));
}
__device__ __forceinline__ void cp_commit() { asm volatile("cp.async.commit_group;" ::: "memory"); }
template <int N> __device__ __forceinline__ void cp_wait() {
    asm volatile("cp.async.wait_group %0;" :: "n"(N) : "memory");
}
__device__ __forceinline__ void ldsm4(uint32_t* r, uint32_t a) {
    asm volatile("ldmatrix.sync.aligned.m8n8.x4.shared.b16 {%0,%1,%2,%3}, [%4];"
        : "=r"(r[0]), "=r"(r[1]), "=r"(r[2]), "=r"(r[3]) : "r"(a));
}
__device__ __forceinline__ void mma16816(float* d, const uint32_t* a, const uint32_t* b) {
    asm volatile(
        "mma.sync.aligned.m16n8k16.row.col.f32.f16.f16.f32 "
        "{%0,%1,%2,%3}, {%4,%5,%6,%7}, {%8,%9}, {%0,%1,%2,%3};"
        : "+f"(d[0]), "+f"(d[1]), "+f"(d[2]), "+f"(d[3])
        : "r"(a[0]), "r"(a[1]), "r"(a[2]), "r"(a[3]), "r"(b[0]), "r"(b[1]));
}
__device__ __forceinline__ void split1(float v, hf& h, hf& l) {
    h = __float2half_rn(v);
    l = __float2half_rn(v - __half2float(h));
}
__device__ __forceinline__ uint32_t swz(int r, int c) {
    return (uint32_t)(r * 64 + ((c ^ ((r >> 1) & 3)) << 4));
}

// ======================= fp16 HMMA GEMM (unchanged from R14) =======================
#define GSTG   24576
#define GSMEM  (4*GSTG)
#define OFF_AL 8192u
#define OFF_BH 16384u

template <int USELO>
__device__ __forceinline__ void load_chunk(
    uint32_t sb, int slot, long k0, int tid,
    const hf* __restrict__ Ah, const hf* __restrict__ Al, long lda, long bm,
    const hf* __restrict__ Bh, long ldb, long bn)
{
    uint32_t base = sb + (uint32_t)slot * GSTG;
    #pragma unroll
    for (int it = 0; it < 2; it++) {
        int u = tid + it * 256;
        int r = u >> 2, c = u & 3;
        uint32_t off = swz(r, c);
        long srcA = (bm + r) * lda + k0 + c * 8;
        cp16(base + off, Ah + srcA);
        if (USELO) cp16(base + OFF_AL + off, Al + srcA);
        cp16(base + OFF_BH + off, Bh + (bn + r) * ldb + k0 + c * 8);
    }
    cp_commit();
}

template <int USELO>
__global__ __launch_bounds__(256, 2) void gemm_tc(
    const hf* __restrict__ Ah, const hf* __restrict__ Al, long lda,
    const hf* __restrict__ Bh, long ldb,
    float* __restrict__ C,
    hf* __restrict__ Oh, hf* __restrict__ Ol,
    long ldc,
    const float* __restrict__ bias,
    const float* __restrict__ res, int resMod, long resLd,
    int K, float scale, int nTm, int nTn, int kvMode,
    int zInner, long aIn, long aOut, long bIn, long bOut, long cIn, long cOut)
{
    extern __shared__ __align__(128) char smem[];
    const uint32_t sb = smem_u32(smem);
    const int tid = threadIdx.x;
    const int wid = tid >> 5;
    const int lane = tid & 31;

    const int z = blockIdx.z;
    const int zi = z % zInner, zo = z / zInner;
    Ah += (long)zi * aIn + (long)zo * aOut;  Al += (long)zi * aIn + (long)zo * aOut;
    Bh += (long)zi * bIn + (long)zo * bOut;
    const long coff = (long)zi * cIn + (long)zo * cOut;
    if (C)  C  += coff;
    if (Oh && !kvMode) { Oh += coff; if (Ol) Ol += coff; }

    const int idx = blockIdx.x;
    const int per = nTm * 8;
    const int band = idx / per, rem = idx % per;
    const long bm = (long)(rem % nTm) * 128;
    const long bn = (long)(band * 8 + rem / nTm) * 128;

    const int wm = wid & 3;
    const int wn = wid >> 2;

    const int aRow = wm * 32 + (lane & 15);
    const int aC0  = (lane >> 4);
    const int bRow = wn * 64 + (lane & 7) + ((lane >> 4) & 1) * 8;
    const int bC0  = ((lane >> 3) & 1);

    float acc[2][8][4];
    #pragma unroll
    for (int i = 0; i < 2; i++)
        #pragma unroll
        for (int j = 0; j < 8; j++)
            #pragma unroll
            for (int q = 0; q < 4; q++) acc[i][j][q] = 0.f;

    const int nCh = K >> 5;
    load_chunk<USELO>(sb, 0, 0,  tid, Ah, Al, lda, bm, Bh, ldb, bn);
    load_chunk<USELO>(sb, 1, 32, tid, Ah, Al, lda, bm, Bh, ldb, bn);
    load_chunk<USELO>(sb, 2, 64, tid, Ah, Al, lda, bm, Bh, ldb, bn);

    for (int i = 0; i < nCh; i++) {
        if (i + 2 < nCh)      cp_wait<2>();
        else if (i + 1 < nCh) cp_wait<1>();
        else                  cp_wait<0>();
        __syncthreads();
        if (i + 3 < nCh)
            load_chunk<USELO>(sb, (i + 3) & 3, (long)(i + 3) * 32, tid,
                              Ah, Al, lda, bm, Bh, ldb, bn);
        const uint32_t stg = sb + (uint32_t)(i & 3) * GSTG;
        #pragma unroll
        for (int ks = 0; ks < 2; ks++) {
            uint32_t ah[2][4], al[2][4];
            #pragma unroll
            for (int m = 0; m < 2; m++) {
                uint32_t a = stg + swz(aRow + m * 16, aC0 + ks * 2);
                ldsm4(ah[m], a);
                if (USELO) ldsm4(al[m], a + OFF_AL);
            }
            #pragma unroll
            for (int p = 0; p < 4; p++) {
                uint32_t bh[4];
                ldsm4(bh, stg + OFF_BH + swz(bRow + p * 16, bC0 + ks * 2));
                #pragma unroll
                for (int m = 0; m < 2; m++)
                    #pragma unroll
                    for (int s = 0; s < 2; s++) {
                        const int nt = p * 2 + s;
                        mma16816(acc[m][nt], ah[m], &bh[s * 2]);
                        if (USELO) mma16816(acc[m][nt], al[m], &bh[s * 2]);
                    }
            }
        }
    }

    const int r0 = lane >> 2;
    const int c0 = (lane & 3) * 2;
    const bool isV = kvMode && (bn >= DD);
    #pragma unroll
    for (int m = 0; m < 2; m++) {
        #pragma unroll
        for (int half = 0; half < 2; half++) {
            const long grow = bm + wm * 32 + m * 16 + r0 + half * 8;
            const long rrow = (grow % resMod) * resLd;
            #pragma unroll
            for (int nt = 0; nt < 8; nt++) {
                const long gcol = bn + wn * 64 + nt * 8 + c0;
                float vx = acc[m][nt][half * 2]     * scale;
                float vy = acc[m][nt][half * 2 + 1] * scale;
                if (bias) {
                    float2 bb = *(const float2*)&bias[gcol];
                    vx += bb.x; vy += bb.y;
                }
                if (res) {
                    float2 rr = *(const float2*)&res[rrow + gcol];
                    vx += rr.x; vy += rr.y;
                }
                if (kvMode) {
                    if (!isV) {
                        __half2 hv; hv.x = __float2half_rn(vx); hv.y = __float2half_rn(vy);
                        *(__half2*)&Oh[grow * DD + gcol] = hv;
                    } else {
                        const int d = (int)(gcol - DD);
                        const long b = grow >> 11;
                        const long s = grow & (DS - 1);
                        const long o = (b * DD + d) * DS + s;
                        Ol[o]      = __float2half_rn(vx);
                        Ol[o + DS] = __float2half_rn(vy);
                    }
                } else {
                    if (C) {
                        float2 v; v.x = vx; v.y = vy;
                        *(float2*)&C[grow * ldc + gcol] = v;
                    }
                    if (Oh) {
                        hf hx, lx, hy, ly;
                        split1(vx, hx, lx); split1(vy, hy, ly);
                        __half2 hv; hv.x = hx; hv.y = hy;
                        *(__half2*)&Oh[grow * ldc + gcol] = hv;
                        if (Ol) {
                            __half2 lv; lv.x = lx; lv.y = ly;
                            *(__half2*)&Ol[grow * ldc + gcol] = lv;
                        }
                    }
                }
            }
        }
    }
}

// ======================= merged split kernel =======================
// All splits are full-matrix contiguous (ldIn == cols). One flat float4 index
// over 8 concatenated segments; per-element math identical to split_mat.
#define NSEG 8
struct SplitArgs {
    const float* in[NSEG];
    hf*          oh[NSEG];
    hf*          ol[NSEG];     // null -> hi only
    long         end[NSEG];    // cumulative end, float4 units
};

__global__ __launch_bounds__(256) void split_many(SplitArgs a, long total4)
{
    long idx = (long)blockIdx.x * 256 + threadIdx.x;
    if (idx >= total4) return;
    int s = 0;
    long base = 0;
    #pragma unroll
    for (int k = 0; k < NSEG; k++) {
        if (idx >= a.end[k]) { s = k + 1; base = a.end[k]; }
    }
    const long off = idx - base;
    float4 v = ((const float4*)a.in[s])[off];
    hf h0, h1, h2, h3, l0, l1, l2, l3;
    split1(v.x, h0, l0); split1(v.y, h1, l1);
    split1(v.z, h2, l2); split1(v.w, h3, l3);
    __half2* ph = (__half2*)(a.oh[s]) + off * 2;
    __half2 t; t.x = h0; t.y = h1; ph[0] = t;
    t.x = h2; t.y = h3; ph[1] = t;
    if (a.ol[s]) {
        __half2* pl = (__half2*)(a.ol[s]) + off * 2;
        t.x = l0; t.y = l1; pl[0] = t;
        t.x = l2; t.y = l3; pl[1] = t;
    }
}

// ======================= reductions =======================
__device__ __forceinline__ float blockSum(float val) {
    __shared__ float sh[32];
    int lane = threadIdx.x & 31, w = threadIdx.x >> 5;
    #pragma unroll
    for (int o = 16; o; o >>= 1) val += __shfl_xor_sync(0xffffffffu, val, o);
    __syncthreads();
    if (lane == 0) sh[w] = val;
    __syncthreads();
    val = (lane < 8) ? sh[lane] : 0.f;
    #pragma unroll
    for (int o = 4; o; o >>= 1) val += __shfl_xor_sync(0xffffffffu, val, o);
    return __shfl_sync(0xffffffffu, val, 0);
}
__device__ __forceinline__ float blockMax(float val) {
    __shared__ float sh[32];
    int lane = threadIdx.x & 31, w = threadIdx.x >> 5;
    #pragma unroll
    for (int o = 16; o; o >>= 1) val = fmaxf(val, __shfl_xor_sync(0xffffffffu, val, o));
    __syncthreads();
    if (lane == 0) sh[w] = val;
    __syncthreads();
    val = (lane < 8) ? sh[lane] : -3.4e38f;
    #pragma unroll
    for (int o = 4; o; o >>= 1) val = fmaxf(val, __shfl_xor_sync(0xffffffffu, val, o));
    return __shfl_sync(0xffffffffu, val, 0);
}

// ---------------- local windowed attention: fp16 qkv -> fp16 hi out ----------------
__global__ __launch_bounds__(256) void local_attn(
    const hf* __restrict__ qkv, const int* __restrict__ mask,
    hf* __restrict__ outH)
{
    const int  bw   = blockIdx.x;
    const int  h    = blockIdx.y;
    const long tok0 = (long)bw * DW;
    const int  LD   = 3 * DD;
    const hf* qb = qkv + tok0 * LD + h * DH_;
    const hf* kb = qkv + tok0 * LD + DD + h * DH_;
    const hf* vb = qkv + tok0 * LD + 2 * DD + h * DH_;

    __shared__ float s[DW][DW + 1];
    __shared__ float msk[DW];
    const int tid = threadIdx.x;
    if (tid < DW) msk[tid] = (mask[tok0 + tid] != 0) ? 0.f : -1e9f;

    #pragma unroll
    for (int p = tid; p < DW * DW; p += 256) {
        int i = p >> 5, j = p & 31;
        const float4* qp = (const float4*)(qb + (long)i * LD);
        const float4* kp = (const float4*)(kb + (long)j * LD);
        float acc = 0.f;
        #pragma unroll 8
        for (int d = 0; d < DH_ / 8; d++) {
            float4 a4 = qp[d], c4 = kp[d];
            const __half2* ah = (const __half2*)&a4;
            const __half2* ch = (const __half2*)&c4;
            #pragma unroll
            for (int q = 0; q < 4; q++) {
                float2 av = __half22float2(ah[q]);
                float2 cv = __half22float2(ch[q]);
                acc += av.x * cv.x + av.y * cv.y;
            }
        }
        s[i][j] = acc;
    }
    __syncthreads();

    if (tid < DW) {
        const int i = tid;
        const float mi = msk[i];
        float r[DW];
        float mx = -3.4e38f;
        #pragma unroll
        for (int j = 0; j < DW; j++) {
            float bias = (mi + msk[j] < -0.5f) ? -1e9f : 0.f;
            r[j] = s[i][j] * SCL + bias;
            mx = fmaxf(mx, r[j]);
        }
        float sum = 0.f;
        #pragma unroll
        for (int j = 0; j < DW; j++) { r[j] = expf(r[j] - mx); sum += r[j]; }
        const float inv = 1.f / sum;
        #pragma unroll
        for (int j = 0; j < DW; j++) s[i][j] = r[j] * inv;
    }
    __syncthreads();

    float2 acc[DW];
    #pragma unroll
    for (int i = 0; i < DW; i++) acc[i] = make_float2(0.f, 0.f);
    for (int j = 0; j < DW; j++) {
        float2 v2 = __half22float2(*(const __half2*)(vb + (long)j * LD + tid * 2));
        #pragma unroll
        for (int i = 0; i < DW; i++) {
            float w = s[i][j];
            acc[i].x += w * v2.x;
            acc[i].y += w * v2.y;
        }
    }
    const long obase = tok0 * DD + h * DH_ + tid * 2;
    #pragma unroll
    for (int i = 0; i < DW; i++) {
        __half2 hv;
        hv.x = __float2half_rn(acc[i].x);
        hv.y = __float2half_rn(acc[i].y);
        *(__half2*)&outH[obase + (long)i * DD] = hv;
    }
}

// ---------------- LayerNorm (vectorized): thread owns 16 contiguous halves ----------------
__global__ __launch_bounds__(256) void layernorm_hf(
    const hf* __restrict__ X, const float* __restrict__ g,
    const float* __restrict__ b, hf* __restrict__ Yh)
{
    const long row = blockIdx.x;
    const int base = threadIdx.x * 16;          // 256 threads * 16 = 4096
    const float4* xp = (const float4*)(X + row * DD + base);
    float4 a0 = xp[0], a1 = xp[1];
    float v[16];
    {
        const __half2* h0 = (const __half2*)&a0;
        const __half2* h1 = (const __half2*)&a1;
        #pragma unroll
        for (int q = 0; q < 4; q++) {
            float2 f0 = __half22float2(h0[q]);
            float2 f1 = __half22float2(h1[q]);
            v[q * 2]     = f0.x; v[q * 2 + 1] = f0.y;
            v[8 + q * 2] = f1.x; v[8 + q * 2 + 1] = f1.y;
        }
    }
    float s = 0.f;
    #pragma unroll
    for (int i = 0; i < 16; i++) s += v[i];
    const float mean = blockSum(s) * (1.f / DD);
    float d2 = 0.f;
    #pragma unroll
    for (int i = 0; i < 16; i++) { float d = v[i] - mean; d2 += d * d; }
    const float var = blockSum(d2) * (1.f / DD);
    const float rs = rsqrtf(var + 1e-5f);

    const float4* gp = (const float4*)(g + base);
    const float4* bp = (const float4*)(b + base);
    hf o[16];
    #pragma unroll
    for (int q = 0; q < 4; q++) {
        float4 gg = gp[q], bb = bp[q];
        o[q*4+0] = __float2half_rn((v[q*4+0] - mean) * rs * gg.x + bb.x);
        o[q*4+1] = __float2half_rn((v[q*4+1] - mean) * rs * gg.y + bb.y);
        o[q*4+2] = __float2half_rn((v[q*4+2] - mean) * rs * gg.z + bb.z);
        o[q*4+3] = __float2half_rn((v[q*4+3] - mean) * rs * gg.w + bb.w);
    }
    float4* yp = (float4*)(Yh + row * DD + base);
    yp[0] = *(const float4*)&o[0];
    yp[1] = *(const float4*)&o[8];
}

// ---------------- global softmax (vectorized): thread owns 8 contiguous keys ----------------
__global__ __launch_bounds__(256) void softmax_hf(
    const hf* __restrict__ sc, const int* __restrict__ mask,
    hf* __restrict__ oh)
{
    const long row = blockIdx.x;
    const int  b   = (int)(row >> 11);
    const int base = threadIdx.x * 8;           // 256 threads * 8 = 2048
    float4 x4 = *(const float4*)(sc + row * DS + base);
    int4 m0 = *(const int4*)(mask + (long)b * DS + base);
    int4 m1 = *(const int4*)(mask + (long)b * DS + base + 4);
    int mm[8] = {m0.x, m0.y, m0.z, m0.w, m1.x, m1.y, m1.z, m1.w};
    float v[8];
    {
        const __half2* hh = (const __half2*)&x4;
        #pragma unroll
        for (int q = 0; q < 4; q++) {
            float2 f = __half22float2(hh[q]);
            v[q * 2] = f.x; v[q * 2 + 1] = f.y;
        }
    }
    float mx = -3.4e38f;
    #pragma unroll
    for (int i = 0; i < 8; i++) {
        v[i] += (mm[i] != 0) ? 0.f : -1e9f;
        mx = fmaxf(mx, v[i]);
    }
    mx = blockMax(mx);
    float s = 0.f;
    #pragma unroll
    for (int i = 0; i < 8; i++) { v[i] = expf(v[i] - mx); s += v[i]; }
    s = blockSum(s);
    const float inv = 1.f / s;
    hf o[8];
    #pragma unroll
    for (int i = 0; i < 8; i++) o[i] = __float2half_rn(v[i] * inv);
    *(float4*)(oh + row * DS + base) = *(const float4*)&o[0];
}

// ======================= launch =======================
extern "C" void kernel_launch(void* const* d_in, const int* in_sizes, int n_in,
                              void* d_out, int out_size)
{
    const float* vlm    = (const float*)d_in[0];
    const int*   mask   = (const int*)d_in[1];
    const float* l_in_w = (const float*)d_in[2];
    const float* l_in_b = (const float*)d_in[3];
    const float* l_out_w= (const float*)d_in[4];
    const float* l_out_b= (const float*)d_in[5];
    const float* l_ng   = (const float*)d_in[6];
    const float* l_nb   = (const float*)d_in[7];
    const float* l_pw   = (const float*)d_in[8];
    const float* l_pb   = (const float*)d_in[9];
    const float* g_in_w = (const float*)d_in[10];
    const float* g_in_b = (const float*)d_in[11];
    const float* g_out_w= (const float*)d_in[12];
    const float* g_out_b= (const float*)d_in[13];
    const float* g_ng   = (const float*)d_in[14];
    const float* g_nb   = (const float*)d_in[15];
    const float* qtok   = (const float*)d_in[16];
    const float* o_pw   = (const float*)d_in[17];
    const float* o_pb   = (const float*)d_in[18];
    float* out = (float*)d_out;

    cudaFuncSetAttribute(gemm_tc<0>, cudaFuncAttributeMaxDynamicSharedMemorySize, GSMEM);
    cudaFuncSetAttribute(gemm_tc<1>, cudaFuncAttributeMaxDynamicSharedMemorySize, GSMEM);

    hf *qkv_h,*y_h,*scr_h,*yg_h,
       *vlm_h,*liw_h,*low_h,*lpw_h,*giw_h,*gow_h,*opw_h,
       *attnl_h,*ln_h,*lf_h,*qtok_h,*qtok_l,
       *qg_h,*kvk_h,*vt_h,*sc_h,*ag_h,*lng_h;
    cudaGetSymbolAddress((void**)&qkv_h, b_qkv_h);
    cudaGetSymbolAddress((void**)&y_h,   b_y_h);
    cudaGetSymbolAddress((void**)&scr_h, b_scr_h);
    cudaGetSymbolAddress((void**)&yg_h,  b_yg_h);
    cudaGetSymbolAddress((void**)&vlm_h, b_vlm_h);
    cudaGetSymbolAddress((void**)&liw_h, b_liw_h);
    cudaGetSymbolAddress((void**)&low_h, b_low_h);
    cudaGetSymbolAddress((void**)&lpw_h, b_lpw_h);
    cudaGetSymbolAddress((void**)&giw_h, b_giw_h);
    cudaGetSymbolAddress((void**)&gow_h, b_gow_h);
    cudaGetSymbolAddress((void**)&opw_h, b_opw_h);
    cudaGetSymbolAddress((void**)&attnl_h, b_attnl_h);
    cudaGetSymbolAddress((void**)&ln_h,  b_ln_h);
    cudaGetSymbolAddress((void**)&lf_h,  b_lf_h);
    cudaGetSymbolAddress((void**)&qtok_h,b_qtok_h);  cudaGetSymbolAddress((void**)&qtok_l,b_qtok_l);
    cudaGetSymbolAddress((void**)&qg_h,  b_qg_h);
    cudaGetSymbolAddress((void**)&kvk_h, b_kvk_h);
    cudaGetSymbolAddress((void**)&vt_h,  b_vt_h);
    cudaGetSymbolAddress((void**)&sc_h,  b_sc_h);
    cudaGetSymbolAddress((void**)&ag_h,  b_ag_h);
    cudaGetSymbolAddress((void**)&lng_h, b_lng_h);

    const dim3 T256(256);
    #define GEMM(UL,Ah,Al,lda,Bh,ldb,C,Oh,Ol,ldc,bias,res,resMod,resLd,K,scale,M,N,kvM,zTot,zInner,aIn,aOut,bIn,bOut,cIn,cOut) \
        gemm_tc<UL><<<dim3(((M)/128)*((N)/128), 1, zTot), T256, GSMEM>>>( \
            Ah, Al, lda, Bh, ldb, C, Oh, Ol, ldc, bias, res, resMod, resLd, \
            K, scale, (M)/128, (N)/128, kvM, zInner, aIn, aOut, bIn, bOut, cIn, cOut)
    #define NOF (const float*)nullptr
    #define NOC (float*)nullptr
    #define NOH (hf*)nullptr

    // ---- single merged split launch for all 8 conversions ----
    {
        SplitArgs sa;
        const float* ins[NSEG] = {vlm, l_in_w, l_out_w, l_pw, g_in_w, g_out_w, o_pw, qtok};
        hf* ohs[NSEG] = {vlm_h, liw_h, low_h, lpw_h, giw_h, gow_h, opw_h, qtok_h};
        hf* ols[NSEG] = {NOH,   NOH,   NOH,   NOH,   NOH,   NOH,   NOH,   qtok_l};
        long n4[NSEG] = {
            (long)NTOK * DD / 4, (long)3 * DD * DD / 4, (long)DD * DD / 4,
            (long)DD * DD / 4,   (long)3 * DD * DD / 4, (long)DD * DD / 4,
            (long)DD * DD / 4,   (long)DT * DD / 4
        };
        long cum = 0;
        for (int i = 0; i < NSEG; i++) {
            sa.in[i] = ins[i]; sa.oh[i] = ohs[i]; sa.ol[i] = ols[i];
            cum += n4[i]; sa.end[i] = cum;
        }
        split_many<<<(unsigned)((cum + 255) / 256), T256>>>(sa, cum);
    }

    // 1) local QKV (1-product), fp16 hi out
    GEMM(0, vlm_h, vlm_h, DD, liw_h, DD, NOC, qkv_h, NOH, 3*DD, l_in_b,
         NOF, 1, 1, DD, 1.f, NTOK, 3*DD, 0, 1, 1, 0,0,0,0,0,0);

    // 2) local windowed attention
    local_attn<<<dim3(DB * (DS / DW), NH), T256>>>(qkv_h, mask, attnl_h);

    // 3) local out_proj + residual(vlm) [1-product], fp16 hi out
    GEMM(0, attnl_h, attnl_h, DD, low_h, DD, NOC, y_h, NOH, DD, l_out_b,
         vlm, NTOK, DD, DD, 1.f, NTOK, DD, 0, 1, 1, 0,0,0,0,0,0);

    // 4) LN local
    layernorm_hf<<<NTOK, T256>>>(y_h, l_ng, l_nb, ln_h);

    // 5) local_proj [1-product]
    GEMM(0, ln_h, ln_h, DD, lpw_h, DD, NOC, lf_h, NOH, DD, l_pb,
         NOF, 1, 1, DD, 1.f, NTOK, DD, 0, 1, 1, 0,0,0,0,0,0);

    // 6) global q [2-product]
    GEMM(1, qtok_h, qtok_l, DD, giw_h, DD, NOC, qg_h, NOH, DD, g_in_b,
         NOF, 1, 1, DD, 1.f, DT, DD, 0, 1, 1, 0,0,0,0,0,0);

    // 7) global k,v (1-product), fused K/V-transpose epilogue
    GEMM(0, lf_h, lf_h, DD, giw_h + (long)DD*DD, DD,
         NOC, kvk_h, vt_h, DD, g_in_b + DD,
         NOF, 1, 1, DD, 1.f, NTOK, 2*DD, 1, 1, 1, 0,0,0,0,0,0);

    // 8) scores [1-product], scaled, fp16 hi out
    GEMM(0, qg_h, qg_h, DD, kvk_h, DD, NOC, scr_h, NOH, DS,
         NOF, NOF, 1, 1,
         DH_, SCL, DT, DS, 0, DB*NH, NH,
         DH_, 0, DH_, (long)DS * DD, (long)DT * DS, (long)NH * DT * DS);

    // 9) softmax
    softmax_hf<<<DB * NH * DT, T256>>>(scr_h, mask, sc_h);

    // 10) AV [1-product]
    GEMM(0, sc_h, sc_h, DS, vt_h, DS, NOC, ag_h, NOH, DD,
         NOF, NOF, 1, 1,
         DS, 1.f, DT, DH_, 0, DB*NH, NH,
         (long)DT * DS, (long)NH * DT * DS, (long)DH_ * DS, (long)DD * DS,
         DH_, (long)DT * DD);

    // 11) global out_proj + residual(qtok) [1-product], fp16 hi out
    GEMM(0, ag_h, ag_h, DD, gow_h, DD, NOC, yg_h, NOH, DD, g_out_b,
         qtok, DT, DD, DD, 1.f, NQ, DD, 0, 1, 1, 0,0,0,0,0,0);

    // 12) LN global
    layernorm_hf<<<NQ, T256>>>(yg_h, g_ng, g_nb, lng_h);

    // 13) output_proj -> d_out (fp32) [1-product]
    GEMM(0, lng_h, lng_h, DD, opw_h, DD, out, NOH, NOH, DD, o_pb,
         NOF, 1, 1, DD, 1.f, NQ, DD, 0, 1, 1, 0,0,0,0,0,0);
}

// round 16
// speedup vs baseline: 1.0455x; 1.0455x over previous
#include <cuda_runtime.h>
#include <cuda_fp16.h>
#include <cstdint>

// ---------------- problem constants ----------------
#define DB   4
#define DS   2048
#define DD   4096
#define DT   256
#define DW   32
#define DH_  512
#define NH   8
#define NTOK (DB*DS)            // 8192
#define NQ   (DB*DT)            // 1024
#define SCL  0.044194173824159216f  // 1/sqrt(512)

typedef __half hf;

// ---------------- device scratch ----------------
__device__ __align__(16) hf b_qkv_h [(long)NTOK*3*DD];
__device__ __align__(16) hf b_y_h   [(long)NTOK*DD];
__device__ __align__(16) hf b_scr_h [(long)DB*NH*DT*DS];
__device__ __align__(16) hf b_yg_h  [(long)NQ*DD];
__device__ __align__(16) hf b_vlm_h  [(long)NTOK*DD];
__device__ __align__(16) hf b_liw_h  [(long)3*DD*DD];
__device__ __align__(16) hf b_low_h  [(long)DD*DD];
__device__ __align__(16) hf b_lpw_h  [(long)DD*DD];
__device__ __align__(16) hf b_giw_h  [(long)3*DD*DD];
__device__ __align__(16) hf b_gow_h  [(long)DD*DD];
__device__ __align__(16) hf b_opw_h  [(long)DD*DD];
__device__ __align__(16) hf b_attnl_h[(long)NTOK*DD];
__device__ __align__(16) hf b_ln_h   [(long)NTOK*DD];
__device__ __align__(16) hf b_lf_h   [(long)NTOK*DD];
__device__ __align__(16) hf b_qtok_h [(long)DT*DD],        b_qtok_l [(long)DT*DD];
__device__ __align__(16) hf b_qg_h   [(long)DT*DD];
__device__ __align__(16) hf b_kvk_h  [(long)NTOK*DD];
__device__ __align__(16) hf b_vt_h   [(long)DB*DD*DS];
__device__ __align__(16) hf b_sc_h   [(long)DB*NH*DT*DS];
__device__ __align__(16) hf b_ag_h   [(long)NQ*DD];
__device__ __align__(16) hf b_lng_h  [(long)NQ*DD];

// ======================= helpers =======================
__device__ __forceinline__ uint32_t smem_u32(const void* p) {
    uint32_t a;
    asm("{ .reg .u64 t; cvta.to.shared.u64 t, %1; cvt.u32.u64 %0, t; }" : "=r"(a) : "l"(p));
    return a;
}
__device__ __forceinline__ void cp16(uint32_t dst, const void* src) {
    asm volatile("cp.async.cg.shared.global [%0], [%1], 16;" :: "r"(dst), "l"(src));
}
__device__ __forceinline__ void cp_commit() { asm volatile("cp.async.commit_group;" ::: "memory"); }
template <int N> __device__ __forceinline__ void cp_wait() {
    asm volatile("cp.async.wait_group %0;" :: "n"(N) : "memory");
}
__device__ __forceinline__ void ldsm4(uint32_t* r, uint32_t a) {
    asm volatile("ldmatrix.sync.aligned.m8n8.x4.shared.b16 {%0,%1,%2,%3}, [%4];"
        : "=r"(r[0]), "=r"(r[1]), "=r"(r[2]), "=r"(r[3]) : "r"(a));
}
__device__ __forceinline__ void mma16816(float* d, const uint32_t* a, const uint32_t* b) {
    asm volatile(
        "mma.sync.aligned.m16n8k16.row.col.f32.f16.f16.f32 "
        "{%0,%1,%2,%3}, {%4,%5,%6,%7}, {%8,%9}, {%0,%1,%2,%3};"
        : "+f"(d[0]), "+f"(d[1]), "+f"(d[2]), "+f"(d[3])
        : "r"(a[0]), "r"(a[1]), "r"(a[2]), "r"(a[3]), "r"(b[0]), "r"(b[1]));
}
__device__ __forceinline__ void split1(float v, hf& h, hf& l) {
    h = __float2half_rn(v);
    l = __float2half_rn(v - __half2float(h));
}
// pitch-128 swizzle: K-chunk 64 (128B rows), 16B unit c in 0..7.
// 8-row ldmatrix groups: (c ^ (r&7)) distinct across the group -> all 32 banks.
__device__ __forceinline__ uint32_t swz128(int r, int c) {
    return (uint32_t)(r * 128 + ((c ^ (r & 7)) << 4));
}

// ======================= fp16 HMMA GEMM (K-chunk 64, 3-stage) =======================
// USELO=0: stage = A(16K)+B(16K)=32K, 3 stages=96K, 2 CTAs/SM.
// USELO=1: stage = A+Al+B=48K, 3 stages=144K, 1 CTA/SM (q-gemm only: 64 blocks).
#define GSMEM0 98304
#define GSMEM1 147456

template <int USELO>
__device__ __forceinline__ void load_chunk(
    uint32_t sb, int slot, long k0, int tid,
    const hf* __restrict__ Ah, const hf* __restrict__ Al, long lda, long bm,
    const hf* __restrict__ Bh, long ldb, long bn)
{
    constexpr uint32_t STG   = USELO ? 49152u : 32768u;
    constexpr uint32_t OFFB  = USELO ? 32768u : 16384u;
    uint32_t base = sb + (uint32_t)slot * STG;
    #pragma unroll
    for (int it = 0; it < 4; it++) {
        int u = tid + it * 256;            // 0..1023
        int r = u >> 3, c = u & 7;         // row 0..127, 16B-col 0..7
        uint32_t off = swz128(r, c);
        long srcA = (bm + r) * lda + k0 + c * 8;
        cp16(base + off, Ah + srcA);
        if (USELO) cp16(base + 16384u + off, Al + srcA);
        cp16(base + OFFB + off, Bh + (bn + r) * ldb + k0 + c * 8);
    }
    cp_commit();
}

template <int USELO>
__global__ __launch_bounds__(256, USELO ? 1 : 2) void gemm_tc(
    const hf* __restrict__ Ah, const hf* __restrict__ Al, long lda,
    const hf* __restrict__ Bh, long ldb,
    float* __restrict__ C,
    hf* __restrict__ Oh, hf* __restrict__ Ol,
    long ldc,
    const float* __restrict__ bias,
    const float* __restrict__ res, int resMod, long resLd,
    int K, float scale, int nTm, int nTn, int kvMode,
    int zInner, long aIn, long aOut, long bIn, long bOut, long cIn, long cOut)
{
    constexpr uint32_t STG   = USELO ? 49152u : 32768u;
    constexpr uint32_t OFFB  = USELO ? 32768u : 16384u;
    extern __shared__ __align__(128) char smem[];
    const uint32_t sb = smem_u32(smem);
    const int tid = threadIdx.x;
    const int wid = tid >> 5;
    const int lane = tid & 31;

    const int z = blockIdx.z;
    const int zi = z % zInner, zo = z / zInner;
    Ah += (long)zi * aIn + (long)zo * aOut;  Al += (long)zi * aIn + (long)zo * aOut;
    Bh += (long)zi * bIn + (long)zo * bOut;
    const long coff = (long)zi * cIn + (long)zo * cOut;
    if (C)  C  += coff;
    if (Oh && !kvMode) { Oh += coff; if (Ol) Ol += coff; }

    const int idx = blockIdx.x;
    const int per = nTm * 8;
    const int band = idx / per, rem = idx % per;
    const long bm = (long)(rem % nTm) * 128;
    const long bn = (long)(band * 8 + rem / nTm) * 128;

    const int wm = wid & 3;
    const int wn = wid >> 2;

    const int aRow = wm * 32 + (lane & 15);                         // + m*16
    const int aC0  = (lane >> 4);                                    // + ks*2
    const int bRow = wn * 64 + (lane & 7) + ((lane >> 4) & 1) * 8;   // + p*16
    const int bC0  = ((lane >> 3) & 1);                              // + ks*2

    float acc[2][8][4];
    #pragma unroll
    for (int i = 0; i < 2; i++)
        #pragma unroll
        for (int j = 0; j < 8; j++)
            #pragma unroll
            for (int q = 0; q < 4; q++) acc[i][j][q] = 0.f;

    const int nCh = K >> 6;        // K-chunk 64; all K divisible by 64
    load_chunk<USELO>(sb, 0, 0,  tid, Ah, Al, lda, bm, Bh, ldb, bn);
    load_chunk<USELO>(sb, 1, 64, tid, Ah, Al, lda, bm, Bh, ldb, bn);

    for (int i = 0; i < nCh; i++) {
        if (i + 1 < nCh) cp_wait<1>(); else cp_wait<0>();
        __syncthreads();
        if (i + 2 < nCh)
            load_chunk<USELO>(sb, (i + 2) % 3, (long)(i + 2) * 64, tid,
                              Ah, Al, lda, bm, Bh, ldb, bn);
        const uint32_t stg = sb + (uint32_t)(i % 3) * STG;
        #pragma unroll
        for (int ks = 0; ks < 4; ks++) {
            uint32_t ah[2][4], al[2][4];
            #pragma unroll
            for (int m = 0; m < 2; m++) {
                uint32_t a = stg + swz128(aRow + m * 16, aC0 + ks * 2);
                ldsm4(ah[m], a);
                if (USELO) {
                    uint32_t a2 = stg + 16384u + swz128(aRow + m * 16, aC0 + ks * 2);
                    ldsm4(al[m], a2);
                }
            }
            #pragma unroll
            for (int p = 0; p < 4; p++) {
                uint32_t bh[4];
                ldsm4(bh, stg + OFFB + swz128(bRow + p * 16, bC0 + ks * 2));
                #pragma unroll
                for (int m = 0; m < 2; m++)
                    #pragma unroll
                    for (int s = 0; s < 2; s++) {
                        const int nt = p * 2 + s;
                        mma16816(acc[m][nt], ah[m], &bh[s * 2]);
                        if (USELO) mma16816(acc[m][nt], al[m], &bh[s * 2]);
                    }
            }
        }
    }

    const int r0 = lane >> 2;
    const int c0 = (lane & 3) * 2;
    const bool isV = kvMode && (bn >= DD);
    #pragma unroll
    for (int m = 0; m < 2; m++) {
        #pragma unroll
        for (int half = 0; half < 2; half++) {
            const long grow = bm + wm * 32 + m * 16 + r0 + half * 8;
            const long rrow = (grow % resMod) * resLd;
            #pragma unroll
            for (int nt = 0; nt < 8; nt++) {
                const long gcol = bn + wn * 64 + nt * 8 + c0;
                float vx = acc[m][nt][half * 2]     * scale;
                float vy = acc[m][nt][half * 2 + 1] * scale;
                if (bias) {
                    float2 bb = *(const float2*)&bias[gcol];
                    vx += bb.x; vy += bb.y;
                }
                if (res) {
                    float2 rr = *(const float2*)&res[rrow + gcol];
                    vx += rr.x; vy += rr.y;
                }
                if (kvMode) {
                    if (!isV) {
                        __half2 hv; hv.x = __float2half_rn(vx); hv.y = __float2half_rn(vy);
                        *(__half2*)&Oh[grow * DD + gcol] = hv;
                    } else {
                        const int d = (int)(gcol - DD);
                        const long b = grow >> 11;
                        const long s = grow & (DS - 1);
                        const long o = (b * DD + d) * DS + s;
                        Ol[o]      = __float2half_rn(vx);
                        Ol[o + DS] = __float2half_rn(vy);
                    }
                } else {
                    if (C) {
                        float2 v; v.x = vx; v.y = vy;
                        *(float2*)&C[grow * ldc + gcol] = v;
                    }
                    if (Oh) {
                        hf hx, lx, hy, ly;
                        split1(vx, hx, lx); split1(vy, hy, ly);
                        __half2 hv; hv.x = hx; hv.y = hy;
                        *(__half2*)&Oh[grow * ldc + gcol] = hv;
                        if (Ol) {
                            __half2 lv; lv.x = lx; lv.y = ly;
                            *(__half2*)&Ol[grow * ldc + gcol] = lv;
                        }
                    }
                }
            }
        }
    }
}

// ======================= merged split kernel =======================
#define NSEG 8
struct SplitArgs {
    const float* in[NSEG];
    hf*          oh[NSEG];
    hf*          ol[NSEG];
    long         end[NSEG];
};

__global__ __launch_bounds__(256) void split_many(SplitArgs a, long total4)
{
    long idx = (long)blockIdx.x * 256 + threadIdx.x;
    if (idx >= total4) return;
    int s = 0;
    long base = 0;
    #pragma unroll
    for (int k = 0; k < NSEG; k++) {
        if (idx >= a.end[k]) { s = k + 1; base = a.end[k]; }
    }
    const long off = idx - base;
    float4 v = ((const float4*)a.in[s])[off];
    hf h0, h1, h2, h3, l0, l1, l2, l3;
    split1(v.x, h0, l0); split1(v.y, h1, l1);
    split1(v.z, h2, l2); split1(v.w, h3, l3);
    __half2* ph = (__half2*)(a.oh[s]) + off * 2;
    __half2 t; t.x = h0; t.y = h1; ph[0] = t;
    t.x = h2; t.y = h3; ph[1] = t;
    if (a.ol[s]) {
        __half2* pl = (__half2*)(a.ol[s]) + off * 2;
        t.x = l0; t.y = l1; pl[0] = t;
        t.x = l2; t.y = l3; pl[1] = t;
    }
}

// ======================= reductions =======================
__device__ __forceinline__ float blockSum(float val) {
    __shared__ float sh[32];
    int lane = threadIdx.x & 31, w = threadIdx.x >> 5;
    #pragma unroll
    for (int o = 16; o; o >>= 1) val += __shfl_xor_sync(0xffffffffu, val, o);
    __syncthreads();
    if (lane == 0) sh[w] = val;
    __syncthreads();
    val = (lane < 8) ? sh[lane] : 0.f;
    #pragma unroll
    for (int o = 4; o; o >>= 1) val += __shfl_xor_sync(0xffffffffu, val, o);
    return __shfl_sync(0xffffffffu, val, 0);
}
__device__ __forceinline__ float blockMax(float val) {
    __shared__ float sh[32];
    int lane = threadIdx.x & 31, w = threadIdx.x >> 5;
    #pragma unroll
    for (int o = 16; o; o >>= 1) val = fmaxf(val, __shfl_xor_sync(0xffffffffu, val, o));
    __syncthreads();
    if (lane == 0) sh[w] = val;
    __syncthreads();
    val = (lane < 8) ? sh[lane] : -3.4e38f;
    #pragma unroll
    for (int o = 4; o; o >>= 1) val = fmaxf(val, __shfl_xor_sync(0xffffffffu, val, o));
    return __shfl_sync(0xffffffffu, val, 0);
}

// ---------------- local windowed attention ----------------
__global__ __launch_bounds__(256) void local_attn(
    const hf* __restrict__ qkv, const int* __restrict__ mask,
    hf* __restrict__ outH)
{
    const int  bw   = blockIdx.x;
    const int  h    = blockIdx.y;
    const long tok0 = (long)bw * DW;
    const int  LD   = 3 * DD;
    const hf* qb = qkv + tok0 * LD + h * DH_;
    const hf* kb = qkv + tok0 * LD + DD + h * DH_;
    const hf* vb = qkv + tok0 * LD + 2 * DD + h * DH_;

    __shared__ float s[DW][DW + 1];
    __shared__ float msk[DW];
    const int tid = threadIdx.x;
    if (tid < DW) msk[tid] = (mask[tok0 + tid] != 0) ? 0.f : -1e9f;

    #pragma unroll
    for (int p = tid; p < DW * DW; p += 256) {
        int i = p >> 5, j = p & 31;
        const float4* qp = (const float4*)(qb + (long)i * LD);
        const float4* kp = (const float4*)(kb + (long)j * LD);
        float acc = 0.f;
        #pragma unroll 8
        for (int d = 0; d < DH_ / 8; d++) {
            float4 a4 = qp[d], c4 = kp[d];
            const __half2* ah = (const __half2*)&a4;
            const __half2* ch = (const __half2*)&c4;
            #pragma unroll
            for (int q = 0; q < 4; q++) {
                float2 av = __half22float2(ah[q]);
                float2 cv = __half22float2(ch[q]);
                acc += av.x * cv.x + av.y * cv.y;
            }
        }
        s[i][j] = acc;
    }
    __syncthreads();

    if (tid < DW) {
        const int i = tid;
        const float mi = msk[i];
        float r[DW];
        float mx = -3.4e38f;
        #pragma unroll
        for (int j = 0; j < DW; j++) {
            float bias = (mi + msk[j] < -0.5f) ? -1e9f : 0.f;
            r[j] = s[i][j] * SCL + bias;
            mx = fmaxf(mx, r[j]);
        }
        float sum = 0.f;
        #pragma unroll
        for (int j = 0; j < DW; j++) { r[j] = expf(r[j] - mx); sum += r[j]; }
        const float inv = 1.f / sum;
        #pragma unroll
        for (int j = 0; j < DW; j++) s[i][j] = r[j] * inv;
    }
    __syncthreads();

    float2 acc[DW];
    #pragma unroll
    for (int i = 0; i < DW; i++) acc[i] = make_float2(0.f, 0.f);
    for (int j = 0; j < DW; j++) {
        float2 v2 = __half22float2(*(const __half2*)(vb + (long)j * LD + tid * 2));
        #pragma unroll
        for (int i = 0; i < DW; i++) {
            float w = s[i][j];
            acc[i].x += w * v2.x;
            acc[i].y += w * v2.y;
        }
    }
    const long obase = tok0 * DD + h * DH_ + tid * 2;
    #pragma unroll
    for (int i = 0; i < DW; i++) {
        __half2 hv;
        hv.x = __float2half_rn(acc[i].x);
        hv.y = __float2half_rn(acc[i].y);
        *(__half2*)&outH[obase + (long)i * DD] = hv;
    }
}

// ---------------- LayerNorm (vectorized) ----------------
__global__ __launch_bounds__(256) void layernorm_hf(
    const hf* __restrict__ X, const float* __restrict__ g,
    const float* __restrict__ b, hf* __restrict__ Yh)
{
    const long row = blockIdx.x;
    const int base = threadIdx.x * 16;
    const float4* xp = (const float4*)(X + row * DD + base);
    float4 a0 = xp[0], a1 = xp[1];
    float v[16];
    {
        const __half2* h0 = (const __half2*)&a0;
        const __half2* h1 = (const __half2*)&a1;
        #pragma unroll
        for (int q = 0; q < 4; q++) {
            float2 f0 = __half22float2(h0[q]);
            float2 f1 = __half22float2(h1[q]);
            v[q * 2]     = f0.x; v[q * 2 + 1] = f0.y;
            v[8 + q * 2] = f1.x; v[8 + q * 2 + 1] = f1.y;
        }
    }
    float s = 0.f;
    #pragma unroll
    for (int i = 0; i < 16; i++) s += v[i];
    const float mean = blockSum(s) * (1.f / DD);
    float d2 = 0.f;
    #pragma unroll
    for (int i = 0; i < 16; i++) { float d = v[i] - mean; d2 += d * d; }
    const float var = blockSum(d2) * (1.f / DD);
    const float rs = rsqrtf(var + 1e-5f);

    const float4* gp = (const float4*)(g + base);
    const float4* bp = (const float4*)(b + base);
    hf o[16];
    #pragma unroll
    for (int q = 0; q < 4; q++) {
        float4 gg = gp[q], bb = bp[q];
        o[q*4+0] = __float2half_rn((v[q*4+0] - mean) * rs * gg.x + bb.x);
        o[q*4+1] = __float2half_rn((v[q*4+1] - mean) * rs * gg.y + bb.y);
        o[q*4+2] = __float2half_rn((v[q*4+2] - mean) * rs * gg.z + bb.z);
        o[q*4+3] = __float2half_rn((v[q*4+3] - mean) * rs * gg.w + bb.w);
    }
    float4* yp = (float4*)(Yh + row * DD + base);
    yp[0] = *(const float4*)&o[0];
    yp[1] = *(const float4*)&o[8];
}

// ---------------- global softmax (vectorized) ----------------
__global__ __launch_bounds__(256) void softmax_hf(
    const hf* __restrict__ sc, const int* __restrict__ mask,
    hf* __restrict__ oh)
{
    const long row = blockIdx.x;
    const int  b   = (int)(row >> 11);
    const int base = threadIdx.x * 8;
    float4 x4 = *(const float4*)(sc + row * DS + base);
    int4 m0 = *(const int4*)(mask + (long)b * DS + base);
    int4 m1 = *(const int4*)(mask + (long)b * DS + base + 4);
    int mm[8] = {m0.x, m0.y, m0.z, m0.w, m1.x, m1.y, m1.z, m1.w};
    float v[8];
    {
        const __half2* hh = (const __half2*)&x4;
        #pragma unroll
        for (int q = 0; q < 4; q++) {
            float2 f = __half22float2(hh[q]);
            v[q * 2] = f.x; v[q * 2 + 1] = f.y;
        }
    }
    float mx = -3.4e38f;
    #pragma unroll
    for (int i = 0; i < 8; i++) {
        v[i] += (mm[i] != 0) ? 0.f : -1e9f;
        mx = fmaxf(mx, v[i]);
    }
    mx = blockMax(mx);
    float s = 0.f;
    #pragma unroll
    for (int i = 0; i < 8; i++) { v[i] = expf(v[i] - mx); s += v[i]; }
    s = blockSum(s);
    const float inv = 1.f / s;
    hf o[8];
    #pragma unroll
    for (int i = 0; i < 8; i++) o[i] = __float2half_rn(v[i] * inv);
    *(float4*)(oh + row * DS + base) = *(const float4*)&o[0];
}

// ======================= launch =======================
extern "C" void kernel_launch(void* const* d_in, const int* in_sizes, int n_in,
                              void* d_out, int out_size)
{
    const float* vlm    = (const float*)d_in[0];
    const int*   mask   = (const int*)d_in[1];
    const float* l_in_w = (const float*)d_in[2];
    const float* l_in_b = (const float*)d_in[3];
    const float* l_out_w= (const float*)d_in[4];
    const float* l_out_b= (const float*)d_in[5];
    const float* l_ng   = (const float*)d_in[6];
    const float* l_nb   = (const float*)d_in[7];
    const float* l_pw   = (const float*)d_in[8];
    const float* l_pb   = (const float*)d_in[9];
    const float* g_in_w = (const float*)d_in[10];
    const float* g_in_b = (const float*)d_in[11];
    const float* g_out_w= (const float*)d_in[12];
    const float* g_out_b= (const float*)d_in[13];
    const float* g_ng   = (const float*)d_in[14];
    const float* g_nb   = (const float*)d_in[15];
    const float* qtok   = (const float*)d_in[16];
    const float* o_pw   = (const float*)d_in[17];
    const float* o_pb   = (const float*)d_in[18];
    float* out = (float*)d_out;

    cudaFuncSetAttribute(gemm_tc<0>, cudaFuncAttributeMaxDynamicSharedMemorySize, GSMEM0);
    cudaFuncSetAttribute(gemm_tc<1>, cudaFuncAttributeMaxDynamicSharedMemorySize, GSMEM1);

    hf *qkv_h,*y_h,*scr_h,*yg_h,
       *vlm_h,*liw_h,*low_h,*lpw_h,*giw_h,*gow_h,*opw_h,
       *attnl_h,*ln_h,*lf_h,*qtok_h,*qtok_l,
       *qg_h,*kvk_h,*vt_h,*sc_h,*ag_h,*lng_h;
    cudaGetSymbolAddress((void**)&qkv_h, b_qkv_h);
    cudaGetSymbolAddress((void**)&y_h,   b_y_h);
    cudaGetSymbolAddress((void**)&scr_h, b_scr_h);
    cudaGetSymbolAddress((void**)&yg_h,  b_yg_h);
    cudaGetSymbolAddress((void**)&vlm_h, b_vlm_h);
    cudaGetSymbolAddress((void**)&liw_h, b_liw_h);
    cudaGetSymbolAddress((void**)&low_h, b_low_h);
    cudaGetSymbolAddress((void**)&lpw_h, b_lpw_h);
    cudaGetSymbolAddress((void**)&giw_h, b_giw_h);
    cudaGetSymbolAddress((void**)&gow_h, b_gow_h);
    cudaGetSymbolAddress((void**)&opw_h, b_opw_h);
    cudaGetSymbolAddress((void**)&attnl_h, b_attnl_h);
    cudaGetSymbolAddress((void**)&ln_h,  b_ln_h);
    cudaGetSymbolAddress((void**)&lf_h,  b_lf_h);
    cudaGetSymbolAddress((void**)&qtok_h,b_qtok_h);  cudaGetSymbolAddress((void**)&qtok_l,b_qtok_l);
    cudaGetSymbolAddress((void**)&qg_h,  b_qg_h);
    cudaGetSymbolAddress((void**)&kvk_h, b_kvk_h);
    cudaGetSymbolAddress((void**)&vt_h,  b_vt_h);
    cudaGetSymbolAddress((void**)&sc_h,  b_sc_h);
    cudaGetSymbolAddress((void**)&ag_h,  b_ag_h);
    cudaGetSymbolAddress((void**)&lng_h, b_lng_h);

    const dim3 T256(256);
    #define GEMM(UL,GS,Ah,Al,lda,Bh,ldb,C,Oh,Ol,ldc,bias,res,resMod,resLd,K,scale,M,N,kvM,zTot,zInner,aIn,aOut,bIn,bOut,cIn,cOut) \
        gemm_tc<UL><<<dim3(((M)/128)*((N)/128), 1, zTot), T256, GS>>>( \
            Ah, Al, lda, Bh, ldb, C, Oh, Ol, ldc, bias, res, resMod, resLd, \
            K, scale, (M)/128, (N)/128, kvM, zInner, aIn, aOut, bIn, bOut, cIn, cOut)
    #define NOF (const float*)nullptr
    #define NOC (float*)nullptr
    #define NOH (hf*)nullptr

    // ---- single merged split launch ----
    {
        SplitArgs sa;
        const float* ins[NSEG] = {vlm, l_in_w, l_out_w, l_pw, g_in_w, g_out_w, o_pw, qtok};
        hf* ohs[NSEG] = {vlm_h, liw_h, low_h, lpw_h, giw_h, gow_h, opw_h, qtok_h};
        hf* ols[NSEG] = {NOH,   NOH,   NOH,   NOH,   NOH,   NOH,   NOH,   qtok_l};
        long n4[NSEG] = {
            (long)NTOK * DD / 4, (long)3 * DD * DD / 4, (long)DD * DD / 4,
            (long)DD * DD / 4,   (long)3 * DD * DD / 4, (long)DD * DD / 4,
            (long)DD * DD / 4,   (long)DT * DD / 4
        };
        long cum = 0;
        for (int i = 0; i < NSEG; i++) {
            sa.in[i] = ins[i]; sa.oh[i] = ohs[i]; sa.ol[i] = ols[i];
            cum += n4[i]; sa.end[i] = cum;
        }
        split_many<<<(unsigned)((cum + 255) / 256), T256>>>(sa, cum);
    }

    // 1) local QKV (1-product), fp16 hi out
    GEMM(0, GSMEM0, vlm_h, vlm_h, DD, liw_h, DD, NOC, qkv_h, NOH, 3*DD, l_in_b,
         NOF, 1, 1, DD, 1.f, NTOK, 3*DD, 0, 1, 1, 0,0,0,0,0,0);

    // 2) local windowed attention
    local_attn<<<dim3(DB * (DS / DW), NH), T256>>>(qkv_h, mask, attnl_h);

    // 3) local out_proj + residual(vlm) [1-product], fp16 hi out
    GEMM(0, GSMEM0, attnl_h, attnl_h, DD, low_h, DD, NOC, y_h, NOH, DD, l_out_b,
         vlm, NTOK, DD, DD, 1.f, NTOK, DD, 0, 1, 1, 0,0,0,0,0,0);

    // 4) LN local
    layernorm_hf<<<NTOK, T256>>>(y_h, l_ng, l_nb, ln_h);

    // 5) local_proj [1-product]
    GEMM(0, GSMEM0, ln_h, ln_h, DD, lpw_h, DD, NOC, lf_h, NOH, DD, l_pb,
         NOF, 1, 1, DD, 1.f, NTOK, DD, 0, 1, 1, 0,0,0,0,0,0);

    // 6) global q [2-product]
    GEMM(1, GSMEM1, qtok_h, qtok_l, DD, giw_h, DD, NOC, qg_h, NOH, DD, g_in_b,
         NOF, 1, 1, DD, 1.f, DT, DD, 0, 1, 1, 0,0,0,0,0,0);

    // 7) global k,v (1-product), fused K/V-transpose epilogue
    GEMM(0, GSMEM0, lf_h, lf_h, DD, giw_h + (long)DD*DD, DD,
         NOC, kvk_h, vt_h, DD, g_in_b + DD,
         NOF, 1, 1, DD, 1.f, NTOK, 2*DD, 1, 1, 1, 0,0,0,0,0,0);

    // 8) scores [1-product], scaled, fp16 hi out
    GEMM(0, GSMEM0, qg_h, qg_h, DD, kvk_h, DD, NOC, scr_h, NOH, DS,
         NOF, NOF, 1, 1,
         DH_, SCL, DT, DS, 0, DB*NH, NH,
         DH_, 0, DH_, (long)DS * DD, (long)DT * DS, (long)NH * DT * DS);

    // 9) softmax
    softmax_hf<<<DB * NH * DT, T256>>>(scr_h, mask, sc_h);

    // 10) AV [1-product]
    GEMM(0, GSMEM0, sc_h, sc_h, DS, vt_h, DS, NOC, ag_h, NOH, DD,
         NOF, NOF, 1, 1,
         DS, 1.f, DT, DH_, 0, DB*NH, NH,
         (long)DT * DS, (long)NH * DT * DS, (long)DH_ * DS, (long)DD * DS,
         DH_, (long)DT * DD);

    // 11) global out_proj + residual(qtok) [1-product], fp16 hi out
    GEMM(0, GSMEM0, ag_h, ag_h, DD, gow_h, DD, NOC, yg_h, NOH, DD, g_out_b,
         qtok, DT, DD, DD, 1.f, NQ, DD, 0, 1, 1, 0,0,0,0,0,0);

    // 12) LN global
    layernorm_hf<<<NQ, T256>>>(yg_h, g_ng, g_nb, lng_h);

    // 13) output_proj -> d_out (fp32) [1-product]
    GEMM(0, GSMEM0, lng_h, lng_h, DD, opw_h, DD, out, NOH, NOH, DD, o_pb,
         NOF, 1, 1, DD, 1.f, NQ, DD, 0, 1, 1, 0,0,0,0,0,0);
}

// round 17
// speedup vs baseline: 1.0638x; 1.0175x over previous
#include <cuda_runtime.h>
#include <cuda_fp16.h>
#include <cstdint>

// ---------------- problem constants ----------------
#define DB   4
#define DS   2048
#define DD   4096
#define DT   256
#define DW   32
#define DH_  512
#define NH   8
#define NTOK (DB*DS)            // 8192
#define NQ   (DB*DT)            // 1024
#define SCL  0.044194173824159216f  // 1/sqrt(512)

typedef __half hf;

// ---------------- device scratch ----------------
__device__ __align__(16) hf b_qkv_h [(long)NTOK*3*DD];
__device__ __align__(16) hf b_y_h   [(long)NTOK*DD];
__device__ __align__(16) hf b_scr_h [(long)DB*NH*DT*DS];
__device__ __align__(16) hf b_yg_h  [(long)NQ*DD];
__device__ __align__(16) hf b_vlm_h  [(long)NTOK*DD];
__device__ __align__(16) hf b_liw_h  [(long)3*DD*DD];
__device__ __align__(16) hf b_low_h  [(long)DD*DD];
__device__ __align__(16) hf b_lpw_h  [(long)DD*DD];
__device__ __align__(16) hf b_giw_h  [(long)3*DD*DD];
__device__ __align__(16) hf b_gow_h  [(long)DD*DD];
__device__ __align__(16) hf b_opw_h  [(long)DD*DD];
__device__ __align__(16) hf b_attnl_h[(long)NTOK*DD];
__device__ __align__(16) hf b_ln_h   [(long)NTOK*DD];
__device__ __align__(16) hf b_lf_h   [(long)NTOK*DD];
__device__ __align__(16) hf b_qtok_h [(long)DT*DD],        b_qtok_l [(long)DT*DD];
__device__ __align__(16) hf b_qg_h   [(long)DT*DD];
__device__ __align__(16) hf b_kvk_h  [(long)NTOK*DD];
__device__ __align__(16) hf b_vt_h   [(long)DB*DD*DS];
__device__ __align__(16) hf b_sc_h   [(long)DB*NH*DT*DS];
__device__ __align__(16) hf b_ag_h   [(long)NQ*DD];
__device__ __align__(16) hf b_lng_h  [(long)NQ*DD];

// ======================= helpers =======================
__device__ __forceinline__ uint32_t smem_u32(const void* p) {
    uint32_t a;
    asm("{ .reg .u64 t; cvta.to.shared.u64 t, %1; cvt.u32.u64 %0, t; }" : "=r"(a) : "l"(p));
    return a;
}
__device__ __forceinline__ void cp16(uint32_t dst, const void* src) {
    asm volatile("cp.async.cg.shared.global [%0], [%1], 16;" :: "r"(dst), "l"(src));
}
__device__ __forceinline__ void cp_commit() { asm volatile("cp.async.commit_group;" ::: "memory"); }
template <int N> __device__ __forceinline__ void cp_wait() {
    asm volatile("cp.async.wait_group %0;" :: "n"(N) : "memory");
}
__device__ __forceinline__ void ldsm4(uint32_t* r, uint32_t a) {
    asm volatile("ldmatrix.sync.aligned.m8n8.x4.shared.b16 {%0,%1,%2,%3}, [%4];"
        : "=r"(r[0]), "=r"(r[1]), "=r"(r[2]), "=r"(r[3]) : "r"(a));
}
__device__ __forceinline__ void mma16816(float* d, const uint32_t* a, const uint32_t* b) {
    asm volatile(
        "mma.sync.aligned.m16n8k16.row.col.f32.f16.f16.f32 "
        "{%0,%1,%2,%3}, {%4,%5,%6,%7}, {%8,%9}, {%0,%1,%2,%3};"
        : "+f"(d[0]), "+f"(d[1]), "+f"(d[2]), "+f"(d[3])
        : "r"(a[0]), "r"(a[1]), "r"(a[2]), "r"(a[3]), "r"(b[0]), "r"(b[1]));
}
__device__ __forceinline__ void split1(float v, hf& h, hf& l) {
    h = __float2half_rn(v);
    l = __float2half_rn(v - __half2float(h));
}
// pitch-128 swizzle: K-chunk 64 (128B rows), 16B unit c in 0..7.
__device__ __forceinline__ uint32_t swz128(int r, int c) {
    return (uint32_t)(r * 128 + ((c ^ (r & 7)) << 4));
}

// ======================= fp16 HMMA GEMM (K-chunk 64, 3-stage, 64x64 warp tiles) =====
// 128 threads / 4 warps, warp layout 2(M) x 2(N), warp tile 64x64 (acc 128 f32).
// USELO=0: stage = A(16K)+B(16K)=32K, 3 stages=96K, 2 CTAs/SM.
// USELO=1: stage = A+Al+B=48K, 3 stages=144K, 1 CTA/SM (q-gemm only).
#define GSMEM0 98304
#define GSMEM1 147456

template <int USELO>
__device__ __forceinline__ void load_chunk(
    uint32_t sb, int slot, long k0, int tid,
    const hf* __restrict__ Ah, const hf* __restrict__ Al, long lda, long bm,
    const hf* __restrict__ Bh, long ldb, long bn)
{
    constexpr uint32_t STG   = USELO ? 49152u : 32768u;
    constexpr uint32_t OFFB  = USELO ? 32768u : 16384u;
    uint32_t base = sb + (uint32_t)slot * STG;
    #pragma unroll
    for (int it = 0; it < 8; it++) {
        int u = tid + it * 128;            // 0..1023
        int r = u >> 3, c = u & 7;         // row 0..127, 16B-col 0..7
        uint32_t off = swz128(r, c);
        long srcA = (bm + r) * lda + k0 + c * 8;
        cp16(base + off, Ah + srcA);
        if (USELO) cp16(base + 16384u + off, Al + srcA);
        cp16(base + OFFB + off, Bh + (bn + r) * ldb + k0 + c * 8);
    }
    cp_commit();
}

template <int USELO>
__global__ __launch_bounds__(128, USELO ? 1 : 2) void gemm_tc(
    const hf* __restrict__ Ah, const hf* __restrict__ Al, long lda,
    const hf* __restrict__ Bh, long ldb,
    float* __restrict__ C,
    hf* __restrict__ Oh, hf* __restrict__ Ol,
    long ldc,
    const float* __restrict__ bias,
    const float* __restrict__ res, int resMod, long resLd,
    int K, float scale, int nTm, int nTn, int kvMode,
    int zInner, long aIn, long aOut, long bIn, long bOut, long cIn, long cOut)
{
    constexpr uint32_t STG   = USELO ? 49152u : 32768u;
    constexpr uint32_t OFFB  = USELO ? 32768u : 16384u;
    extern __shared__ __align__(128) char smem[];
    const uint32_t sb = smem_u32(smem);
    const int tid = threadIdx.x;
    const int wid = tid >> 5;
    const int lane = tid & 31;

    const int z = blockIdx.z;
    const int zi = z % zInner, zo = z / zInner;
    Ah += (long)zi * aIn + (long)zo * aOut;  Al += (long)zi * aIn + (long)zo * aOut;
    Bh += (long)zi * bIn + (long)zo * bOut;
    const long coff = (long)zi * cIn + (long)zo * cOut;
    if (C)  C  += coff;
    if (Oh && !kvMode) { Oh += coff; if (Ol) Ol += coff; }

    const int idx = blockIdx.x;
    const int per = nTm * 8;
    const int band = idx / per, rem = idx % per;
    const long bm = (long)(rem % nTm) * 128;
    const long bn = (long)(band * 8 + rem / nTm) * 128;

    // warp layout: 2(M) x 2(N); warp tile 64x64
    const int wm = wid & 1;
    const int wn = wid >> 1;

    const int aRow = wm * 64 + (lane & 15);                         // + m*16
    const int aC0  = (lane >> 4);                                    // + ks*2
    const int bRow = wn * 64 + (lane & 7) + ((lane >> 4) & 1) * 8;   // + p*16
    const int bC0  = ((lane >> 3) & 1);                              // + ks*2

    float acc[4][8][4];
    #pragma unroll
    for (int i = 0; i < 4; i++)
        #pragma unroll
        for (int j = 0; j < 8; j++)
            #pragma unroll
            for (int q = 0; q < 4; q++) acc[i][j][q] = 0.f;

    const int nCh = K >> 6;        // K-chunk 64
    load_chunk<USELO>(sb, 0, 0,  tid, Ah, Al, lda, bm, Bh, ldb, bn);
    load_chunk<USELO>(sb, 1, 64, tid, Ah, Al, lda, bm, Bh, ldb, bn);

    for (int i = 0; i < nCh; i++) {
        if (i + 1 < nCh) cp_wait<1>(); else cp_wait<0>();
        __syncthreads();
        if (i + 2 < nCh)
            load_chunk<USELO>(sb, (i + 2) % 3, (long)(i + 2) * 64, tid,
                              Ah, Al, lda, bm, Bh, ldb, bn);
        const uint32_t stg = sb + (uint32_t)(i % 3) * STG;
        #pragma unroll
        for (int ks = 0; ks < 4; ks++) {
            uint32_t ah[4][4], al[4][4], bh[4][4];
            #pragma unroll
            for (int m = 0; m < 4; m++) {
                uint32_t a = stg + swz128(aRow + m * 16, aC0 + ks * 2);
                ldsm4(ah[m], a);
                if (USELO) ldsm4(al[m], a + 16384u);
            }
            #pragma unroll
            for (int p = 0; p < 4; p++)
                ldsm4(bh[p], stg + OFFB + swz128(bRow + p * 16, bC0 + ks * 2));
            #pragma unroll
            for (int m = 0; m < 4; m++)
                #pragma unroll
                for (int nt = 0; nt < 8; nt++) {
                    mma16816(acc[m][nt], ah[m], &bh[nt >> 1][(nt & 1) * 2]);
                    if (USELO) mma16816(acc[m][nt], al[m], &bh[nt >> 1][(nt & 1) * 2]);
                }
        }
    }

    const int r0 = lane >> 2;
    const int c0 = (lane & 3) * 2;
    const bool isV = kvMode && (bn >= DD);
    #pragma unroll
    for (int m = 0; m < 4; m++) {
        #pragma unroll
        for (int half = 0; half < 2; half++) {
            const long grow = bm + wm * 64 + m * 16 + r0 + half * 8;
            const long rrow = (grow % resMod) * resLd;
            #pragma unroll
            for (int nt = 0; nt < 8; nt++) {
                const long gcol = bn + wn * 64 + nt * 8 + c0;
                float vx = acc[m][nt][half * 2]     * scale;
                float vy = acc[m][nt][half * 2 + 1] * scale;
                if (bias) {
                    float2 bb = *(const float2*)&bias[gcol];
                    vx += bb.x; vy += bb.y;
                }
                if (res) {
                    float2 rr = *(const float2*)&res[rrow + gcol];
                    vx += rr.x; vy += rr.y;
                }
                if (kvMode) {
                    if (!isV) {
                        __half2 hv; hv.x = __float2half_rn(vx); hv.y = __float2half_rn(vy);
                        *(__half2*)&Oh[grow * DD + gcol] = hv;
                    } else {
                        const int d = (int)(gcol - DD);
                        const long b = grow >> 11;
                        const long s = grow & (DS - 1);
                        const long o = (b * DD + d) * DS + s;
                        Ol[o]      = __float2half_rn(vx);
                        Ol[o + DS] = __float2half_rn(vy);
                    }
                } else {
                    if (C) {
                        float2 v; v.x = vx; v.y = vy;
                        *(float2*)&C[grow * ldc + gcol] = v;
                    }
                    if (Oh) {
                        hf hx, lx, hy, ly;
                        split1(vx, hx, lx); split1(vy, hy, ly);
                        __half2 hv; hv.x = hx; hv.y = hy;
                        *(__half2*)&Oh[grow * ldc + gcol] = hv;
                        if (Ol) {
                            __half2 lv; lv.x = lx; lv.y = ly;
                            *(__half2*)&Ol[grow * ldc + gcol] = lv;
                        }
                    }
                }
            }
        }
    }
}

// ======================= merged split kernel =======================
#define NSEG 8
struct SplitArgs {
    const float* in[NSEG];
    hf*          oh[NSEG];
    hf*          ol[NSEG];
    long         end[NSEG];
};

__global__ __launch_bounds__(256) void split_many(SplitArgs a, long total4)
{
    long idx = (long)blockIdx.x * 256 + threadIdx.x;
    if (idx >= total4) return;
    int s = 0;
    long base = 0;
    #pragma unroll
    for (int k = 0; k < NSEG; k++) {
        if (idx >= a.end[k]) { s = k + 1; base = a.end[k]; }
    }
    const long off = idx - base;
    float4 v = ((const float4*)a.in[s])[off];
    hf h0, h1, h2, h3, l0, l1, l2, l3;
    split1(v.x, h0, l0); split1(v.y, h1, l1);
    split1(v.z, h2, l2); split1(v.w, h3, l3);
    __half2* ph = (__half2*)(a.oh[s]) + off * 2;
    __half2 t; t.x = h0; t.y = h1; ph[0] = t;
    t.x = h2; t.y = h3; ph[1] = t;
    if (a.ol[s]) {
        __half2* pl = (__half2*)(a.ol[s]) + off * 2;
        t.x = l0; t.y = l1; pl[0] = t;
        t.x = l2; t.y = l3; pl[1] = t;
    }
}

// ======================= reductions =======================
__device__ __forceinline__ float blockSum(float val) {
    __shared__ float sh[32];
    int lane = threadIdx.x & 31, w = threadIdx.x >> 5;
    #pragma unroll
    for (int o = 16; o; o >>= 1) val += __shfl_xor_sync(0xffffffffu, val, o);
    __syncthreads();
    if (lane == 0) sh[w] = val;
    __syncthreads();
    val = (lane < 8) ? sh[lane] : 0.f;
    #pragma unroll
    for (int o = 4; o; o >>= 1) val += __shfl_xor_sync(0xffffffffu, val, o);
    return __shfl_sync(0xffffffffu, val, 0);
}
__device__ __forceinline__ float blockMax(float val) {
    __shared__ float sh[32];
    int lane = threadIdx.x & 31, w = threadIdx.x >> 5;
    #pragma unroll
    for (int o = 16; o; o >>= 1) val = fmaxf(val, __shfl_xor_sync(0xffffffffu, val, o));
    __syncthreads();
    if (lane == 0) sh[w] = val;
    __syncthreads();
    val = (lane < 8) ? sh[lane] : -3.4e38f;
    #pragma unroll
    for (int o = 4; o; o >>= 1) val = fmaxf(val, __shfl_xor_sync(0xffffffffu, val, o));
    return __shfl_sync(0xffffffffu, val, 0);
}

// ---------------- local windowed attention ----------------
__global__ __launch_bounds__(256) void local_attn(
    const hf* __restrict__ qkv, const int* __restrict__ mask,
    hf* __restrict__ outH)
{
    const int  bw   = blockIdx.x;
    const int  h    = blockIdx.y;
    const long tok0 = (long)bw * DW;
    const int  LD   = 3 * DD;
    const hf* qb = qkv + tok0 * LD + h * DH_;
    const hf* kb = qkv + tok0 * LD + DD + h * DH_;
    const hf* vb = qkv + tok0 * LD + 2 * DD + h * DH_;

    __shared__ float s[DW][DW + 1];
    __shared__ float msk[DW];
    const int tid = threadIdx.x;
    if (tid < DW) msk[tid] = (mask[tok0 + tid] != 0) ? 0.f : -1e9f;

    #pragma unroll
    for (int p = tid; p < DW * DW; p += 256) {
        int i = p >> 5, j = p & 31;
        const float4* qp = (const float4*)(qb + (long)i * LD);
        const float4* kp = (const float4*)(kb + (long)j * LD);
        float acc = 0.f;
        #pragma unroll 8
        for (int d = 0; d < DH_ / 8; d++) {
            float4 a4 = qp[d], c4 = kp[d];
            const __half2* ah = (const __half2*)&a4;
            const __half2* ch = (const __half2*)&c4;
            #pragma unroll
            for (int q = 0; q < 4; q++) {
                float2 av = __half22float2(ah[q]);
                float2 cv = __half22float2(ch[q]);
                acc += av.x * cv.x + av.y * cv.y;
            }
        }
        s[i][j] = acc;
    }
    __syncthreads();

    if (tid < DW) {
        const int i = tid;
        const float mi = msk[i];
        float r[DW];
        float mx = -3.4e38f;
        #pragma unroll
        for (int j = 0; j < DW; j++) {
            float bias = (mi + msk[j] < -0.5f) ? -1e9f : 0.f;
            r[j] = s[i][j] * SCL + bias;
            mx = fmaxf(mx, r[j]);
        }
        float sum = 0.f;
        #pragma unroll
        for (int j = 0; j < DW; j++) { r[j] = expf(r[j] - mx); sum += r[j]; }
        const float inv = 1.f / sum;
        #pragma unroll
        for (int j = 0; j < DW; j++) s[i][j] = r[j] * inv;
    }
    __syncthreads();

    float2 acc[DW];
    #pragma unroll
    for (int i = 0; i < DW; i++) acc[i] = make_float2(0.f, 0.f);
    for (int j = 0; j < DW; j++) {
        float2 v2 = __half22float2(*(const __half2*)(vb + (long)j * LD + tid * 2));
        #pragma unroll
        for (int i = 0; i < DW; i++) {
            float w = s[i][j];
            acc[i].x += w * v2.x;
            acc[i].y += w * v2.y;
        }
    }
    const long obase = tok0 * DD + h * DH_ + tid * 2;
    #pragma unroll
    for (int i = 0; i < DW; i++) {
        __half2 hv;
        hv.x = __float2half_rn(acc[i].x);
        hv.y = __float2half_rn(acc[i].y);
        *(__half2*)&outH[obase + (long)i * DD] = hv;
    }
}

// ---------------- LayerNorm (vectorized) ----------------
__global__ __launch_bounds__(256) void layernorm_hf(
    const hf* __restrict__ X, const float* __restrict__ g,
    const float* __restrict__ b, hf* __restrict__ Yh)
{
    const long row = blockIdx.x;
    const int base = threadIdx.x * 16;
    const float4* xp = (const float4*)(X + row * DD + base);
    float4 a0 = xp[0], a1 = xp[1];
    float v[16];
    {
        const __half2* h0 = (const __half2*)&a0;
        const __half2* h1 = (const __half2*)&a1;
        #pragma unroll
        for (int q = 0; q < 4; q++) {
            float2 f0 = __half22float2(h0[q]);
            float2 f1 = __half22float2(h1[q]);
            v[q * 2]     = f0.x; v[q * 2 + 1] = f0.y;
            v[8 + q * 2] = f1.x; v[8 + q * 2 + 1] = f1.y;
        }
    }
    float s = 0.f;
    #pragma unroll
    for (int i = 0; i < 16; i++) s += v[i];
    const float mean = blockSum(s) * (1.f / DD);
    float d2 = 0.f;
    #pragma unroll
    for (int i = 0; i < 16; i++) { float d = v[i] - mean; d2 += d * d; }
    const float var = blockSum(d2) * (1.f / DD);
    const float rs = rsqrtf(var + 1e-5f);

    const float4* gp = (const float4*)(g + base);
    const float4* bp = (const float4*)(b + base);
    hf o[16];
    #pragma unroll
    for (int q = 0; q < 4; q++) {
        float4 gg = gp[q], bb = bp[q];
        o[q*4+0] = __float2half_rn((v[q*4+0] - mean) * rs * gg.x + bb.x);
        o[q*4+1] = __float2half_rn((v[q*4+1] - mean) * rs * gg.y + bb.y);
        o[q*4+2] = __float2half_rn((v[q*4+2] - mean) * rs * gg.z + bb.z);
        o[q*4+3] = __float2half_rn((v[q*4+3] - mean) * rs * gg.w + bb.w);
    }
    float4* yp = (float4*)(Yh + row * DD + base);
    yp[0] = *(const float4*)&o[0];
    yp[1] = *(const float4*)&o[8];
}

// ---------------- global softmax (vectorized) ----------------
__global__ __launch_bounds__(256) void softmax_hf(
    const hf* __restrict__ sc, const int* __restrict__ mask,
    hf* __restrict__ oh)
{
    const long row = blockIdx.x;
    const int  b   = (int)(row >> 11);
    const int base = threadIdx.x * 8;
    float4 x4 = *(const float4*)(sc + row * DS + base);
    int4 m0 = *(const int4*)(mask + (long)b * DS + base);
    int4 m1 = *(const int4*)(mask + (long)b * DS + base + 4);
    int mm[8] = {m0.x, m0.y, m0.z, m0.w, m1.x, m1.y, m1.z, m1.w};
    float v[8];
    {
        const __half2* hh = (const __half2*)&x4;
        #pragma unroll
        for (int q = 0; q < 4; q++) {
            float2 f = __half22float2(hh[q]);
            v[q * 2] = f.x; v[q * 2 + 1] = f.y;
        }
    }
    float mx = -3.4e38f;
    #pragma unroll
    for (int i = 0; i < 8; i++) {
        v[i] += (mm[i] != 0) ? 0.f : -1e9f;
        mx = fmaxf(mx, v[i]);
    }
    mx = blockMax(mx);
    float s = 0.f;
    #pragma unroll
    for (int i = 0; i < 8; i++) { v[i] = expf(v[i] - mx); s += v[i]; }
    s = blockSum(s);
    const float inv = 1.f / s;
    hf o[8];
    #pragma unroll
    for (int i = 0; i < 8; i++) o[i] = __float2half_rn(v[i] * inv);
    *(float4*)(oh + row * DS + base) = *(const float4*)&o[0];
}

// ======================= launch =======================
extern "C" void kernel_launch(void* const* d_in, const int* in_sizes, int n_in,
                              void* d_out, int out_size)
{
    const float* vlm    = (const float*)d_in[0];
    const int*   mask   = (const int*)d_in[1];
    const float* l_in_w = (const float*)d_in[2];
    const float* l_in_b = (const float*)d_in[3];
    const float* l_out_w= (const float*)d_in[4];
    const float* l_out_b= (const float*)d_in[5];
    const float* l_ng   = (const float*)d_in[6];
    const float* l_nb   = (const float*)d_in[7];
    const float* l_pw   = (const float*)d_in[8];
    const float* l_pb   = (const float*)d_in[9];
    const float* g_in_w = (const float*)d_in[10];
    const float* g_in_b = (const float*)d_in[11];
    const float* g_out_w= (const float*)d_in[12];
    const float* g_out_b= (const float*)d_in[13];
    const float* g_ng   = (const float*)d_in[14];
    const float* g_nb   = (const float*)d_in[15];
    const float* qtok   = (const float*)d_in[16];
    const float* o_pw   = (const float*)d_in[17];
    const float* o_pb   = (const float*)d_in[18];
    float* out = (float*)d_out;

    cudaFuncSetAttribute(gemm_tc<0>, cudaFuncAttributeMaxDynamicSharedMemorySize, GSMEM0);
    cudaFuncSetAttribute(gemm_tc<1>, cudaFuncAttributeMaxDynamicSharedMemorySize, GSMEM1);

    hf *qkv_h,*y_h,*scr_h,*yg_h,
       *vlm_h,*liw_h,*low_h,*lpw_h,*giw_h,*gow_h,*opw_h,
       *attnl_h,*ln_h,*lf_h,*qtok_h,*qtok_l,
       *qg_h,*kvk_h,*vt_h,*sc_h,*ag_h,*lng_h;
    cudaGetSymbolAddress((void**)&qkv_h, b_qkv_h);
    cudaGetSymbolAddress((void**)&y_h,   b_y_h);
    cudaGetSymbolAddress((void**)&scr_h, b_scr_h);
    cudaGetSymbolAddress((void**)&yg_h,  b_yg_h);
    cudaGetSymbolAddress((void**)&vlm_h, b_vlm_h);
    cudaGetSymbolAddress((void**)&liw_h, b_liw_h);
    cudaGetSymbolAddress((void**)&low_h, b_low_h);
    cudaGetSymbolAddress((void**)&lpw_h, b_lpw_h);
    cudaGetSymbolAddress((void**)&giw_h, b_giw_h);
    cudaGetSymbolAddress((void**)&gow_h, b_gow_h);
    cudaGetSymbolAddress((void**)&opw_h, b_opw_h);
    cudaGetSymbolAddress((void**)&attnl_h, b_attnl_h);
    cudaGetSymbolAddress((void**)&ln_h,  b_ln_h);
    cudaGetSymbolAddress((void**)&lf_h,  b_lf_h);
    cudaGetSymbolAddress((void**)&qtok_h,b_qtok_h);  cudaGetSymbolAddress((void**)&qtok_l,b_qtok_l);
    cudaGetSymbolAddress((void**)&qg_h,  b_qg_h);
    cudaGetSymbolAddress((void**)&kvk_h, b_kvk_h);
    cudaGetSymbolAddress((void**)&vt_h,  b_vt_h);
    cudaGetSymbolAddress((void**)&sc_h,  b_sc_h);
    cudaGetSymbolAddress((void**)&ag_h,  b_ag_h);
    cudaGetSymbolAddress((void**)&lng_h, b_lng_h);

    const dim3 T256(256);
    const dim3 T128(128);
    #define GEMM(UL,GS,Ah,Al,lda,Bh,ldb,C,Oh,Ol,ldc,bias,res,resMod,resLd,K,scale,M,N,kvM,zTot,zInner,aIn,aOut,bIn,bOut,cIn,cOut) \
        gemm_tc<UL><<<dim3(((M)/128)*((N)/128), 1, zTot), T128, GS>>>( \
            Ah, Al, lda, Bh, ldb, C, Oh, Ol, ldc, bias, res, resMod, resLd, \
            K, scale, (M)/128, (N)/128, kvM, zInner, aIn, aOut, bIn, bOut, cIn, cOut)
    #define NOF (const float*)nullptr
    #define NOC (float*)nullptr
    #define NOH (hf*)nullptr

    // ---- single merged split launch ----
    {
        SplitArgs sa;
        const float* ins[NSEG] = {vlm, l_in_w, l_out_w, l_pw, g_in_w, g_out_w, o_pw, qtok};
        hf* ohs[NSEG] = {vlm_h, liw_h, low_h, lpw_h, giw_h, gow_h, opw_h, qtok_h};
        hf* ols[NSEG] = {NOH,   NOH,   NOH,   NOH,   NOH,   NOH,   NOH,   qtok_l};
        long n4[NSEG] = {
            (long)NTOK * DD / 4, (long)3 * DD * DD / 4, (long)DD * DD / 4,
            (long)DD * DD / 4,   (long)3 * DD * DD / 4, (long)DD * DD / 4,
            (long)DD * DD / 4,   (long)DT * DD / 4
        };
        long cum = 0;
        for (int i = 0; i < NSEG; i++) {
            sa.in[i] = ins[i]; sa.oh[i] = ohs[i]; sa.ol[i] = ols[i];
            cum += n4[i]; sa.end[i] = cum;
        }
        split_many<<<(unsigned)((cum + 255) / 256), T256>>>(sa, cum);
    }

    // 1) local QKV (1-product), fp16 hi out
    GEMM(0, GSMEM0, vlm_h, vlm_h, DD, liw_h, DD, NOC, qkv_h, NOH, 3*DD, l_in_b,
         NOF, 1, 1, DD, 1.f, NTOK, 3*DD, 0, 1, 1, 0,0,0,0,0,0);

    // 2) local windowed attention
    local_attn<<<dim3(DB * (DS / DW), NH), T256>>>(qkv_h, mask, attnl_h);

    // 3) local out_proj + residual(vlm) [1-product], fp16 hi out
    GEMM(0, GSMEM0, attnl_h, attnl_h, DD, low_h, DD, NOC, y_h, NOH, DD, l_out_b,
         vlm, NTOK, DD, DD, 1.f, NTOK, DD, 0, 1, 1, 0,0,0,0,0,0);

    // 4) LN local
    layernorm_hf<<<NTOK, T256>>>(y_h, l_ng, l_nb, ln_h);

    // 5) local_proj [1-product]
    GEMM(0, GSMEM0, ln_h, ln_h, DD, lpw_h, DD, NOC, lf_h, NOH, DD, l_pb,
         NOF, 1, 1, DD, 1.f, NTOK, DD, 0, 1, 1, 0,0,0,0,0,0);

    // 6) global q [2-product]
    GEMM(1, GSMEM1, qtok_h, qtok_l, DD, giw_h, DD, NOC, qg_h, NOH, DD, g_in_b,
         NOF, 1, 1, DD, 1.f, DT, DD, 0, 1, 1, 0,0,0,0,0,0);

    // 7) global k,v (1-product), fused K/V-transpose epilogue
    GEMM(0, GSMEM0, lf_h, lf_h, DD, giw_h + (long)DD*DD, DD,
         NOC, kvk_h, vt_h, DD, g_in_b + DD,
         NOF, 1, 1, DD, 1.f, NTOK, 2*DD, 1, 1, 1, 0,0,0,0,0,0);

    // 8) scores [1-product], scaled, fp16 hi out
    GEMM(0, GSMEM0, qg_h, qg_h, DD, kvk_h, DD, NOC, scr_h, NOH, DS,
         NOF, NOF, 1, 1,
         DH_, SCL, DT, DS, 0, DB*NH, NH,
         DH_, 0, DH_, (long)DS * DD, (long)DT * DS, (long)NH * DT * DS);

    // 9) softmax
    softmax_hf<<<DB * NH * DT, T256>>>(scr_h, mask, sc_h);

    // 10) AV [1-product]
    GEMM(0, GSMEM0, sc_h, sc_h, DS, vt_h, DS, NOC, ag_h, NOH, DD,
         NOF, NOF, 1, 1,
         DS, 1.f, DT, DH_, 0, DB*NH, NH,
         (long)DT * DS, (long)NH * DT * DS, (long)DH_ * DS, (long)DD * DS,
         DH_, (long)DT * DD);

    // 11) global out_proj + residual(qtok) [1-product], fp16 hi out
    GEMM(0, GSMEM0, ag_h, ag_h, DD, gow_h, DD, NOC, yg_h, NOH, DD, g_out_b,
         qtok, DT, DD, DD, 1.f, NQ, DD, 0, 1, 1, 0,0,0,0,0,0);

    // 12) LN global
    layernorm_hf<<<NQ, T256>>>(yg_h, g_ng, g_nb, lng_h);

    // 13) output_proj -> d_out (fp32) [1-product]
    GEMM(0, GSMEM0, lng_h, lng_h, DD, opw_h, DD, out, NOH, NOH, DD, o_pb,
         NOF, 1, 1, DD, 1.f, NQ, DD, 0, 1, 1, 0,0,0,0,0,0);
}